// round 15
// baseline (speedup 1.0000x reference)
#include <cuda_runtime.h>
#include <cuda_bf16.h>
#include <math.h>
#include <stdint.h>

// Problem constants
#define BB 16
#define CC 1024
#define DD 768
#define TAU_INV 10.0f
#define KHARD 306
#define KRAND 717
#define SLOTS_PER_B 128
#define MAXP (BB * SLOTS_PER_B)   // 2048

// Split-bf16: rows stored as [hi|lo], K=1536 bf16 = 3072 B/row.
// GEMM: 12 physical k-chunks; each loads hiA/loA/hiB/loB tiles once and runs
// 3 MMA passes (hiA.hiB + hiA.loB + loA.hiB) from the same smem.
#define ROWB 3072
#define NPHYS 12
#define TB 16384                  // one 128x128B tile
#define STAGE_BYTES (4 * TB)      // 64 KB: hiA loA hiB loB
#define NSTAGE 3
#define DYN_SMEM (NSTAGE * STAGE_BYTES)   // 192 KB

// Static device scratch (zero-init at load; unused slot rows never written)
__device__ __align__(128) unsigned char g_Ab[(size_t)MAXP * ROWB];   // 6.3 MB
__device__ __align__(128) unsigned char g_Bb[(size_t)CC * ROWB];     // 3.1 MB
__device__ float g_S[(size_t)MAXP * CC];
__device__ int   g_posList[MAXP];
__device__ int   g_posCount[BB];
__device__ unsigned char g_randFlag[BB * CC];
__device__ float g_term[MAXP];

// ---------------------------------------------------------------------------
// helpers
// ---------------------------------------------------------------------------
__device__ __forceinline__ uint32_t smem_u32(const void* p) {
    uint32_t a;
    asm("{ .reg .u64 t; cvta.to.shared.u64 t, %1; cvt.u32.u64 %0, t; }" : "=r"(a) : "l"(p));
    return a;
}
__device__ __forceinline__ void cp16(uint32_t dst, const void* src) {
    asm volatile("cp.async.ca.shared.global [%0], [%1], 16;" :: "r"(dst), "l"(src) : "memory");
}
__device__ __forceinline__ void ldsm_x4(uint32_t& r0, uint32_t& r1, uint32_t& r2, uint32_t& r3,
                                        uint32_t a) {
    asm volatile("ldmatrix.sync.aligned.m8n8.x4.shared.b16 {%0,%1,%2,%3}, [%4];"
                 : "=r"(r0), "=r"(r1), "=r"(r2), "=r"(r3) : "r"(a));
}
__device__ __forceinline__ void ldsm_x2(uint32_t& r0, uint32_t& r1, uint32_t a) {
    asm volatile("ldmatrix.sync.aligned.m8n8.x2.shared.b16 {%0,%1}, [%2];"
                 : "=r"(r0), "=r"(r1) : "r"(a));
}
__device__ __forceinline__ void mma16816(float* c, const uint32_t* a, const uint32_t* b) {
    asm volatile("mma.sync.aligned.m16n8k16.row.col.f32.bf16.bf16.f32 "
                 "{%0,%1,%2,%3}, {%4,%5,%6,%7}, {%8,%9}, {%0,%1,%2,%3};"
                 : "+f"(c[0]), "+f"(c[1]), "+f"(c[2]), "+f"(c[3])
                 : "r"(a[0]), "r"(a[1]), "r"(a[2]), "r"(a[3]), "r"(b[0]), "r"(b[1]));
}
// order-preserving float<->uint key
__device__ __forceinline__ unsigned fkey(float f) {
    unsigned u = __float_as_uint(f);
    return (u & 0x80000000u) ? ~u : (u | 0x80000000u);
}
__device__ __forceinline__ float funkey(unsigned u) {
    return __uint_as_float((u & 0x80000000u) ? (u & 0x7fffffffu) : ~u);
}

union BF8 { __nv_bfloat16 h[8]; uint4 u; };

// ---------------------------------------------------------------------------
// Kernel 0 (3-way fused):
//  blocks [0,CC):            normalize proto row e, split bf16, g_Bb [hi|lo]
//  blocks [CC,CC+BB):        per-batch compaction + exact random top-KRAND
//  blocks [CC+BB, +BB*CC):   anchor (b,c): if positive, SELF-RANK (count
//                            positives before c), normalize f row, g_Ab [hi|lo]
// ---------------------------------------------------------------------------
__global__ void k_prep(const float* __restrict__ p,
                       const float* __restrict__ f,
                       const int* __restrict__ targets,
                       const float* __restrict__ rsc) {
    int tid = threadIdx.x;
    if (blockIdx.x < CC) {
        int e = blockIdx.x;
        const float4* row = (const float4*)(p + (size_t)e * DD);
        float4 v0 = make_float4(0,0,0,0), v1 = make_float4(0,0,0,0);
        float ss = 0.f;
        if (tid < 96) {
            v0 = row[tid * 2]; v1 = row[tid * 2 + 1];
            ss = v0.x*v0.x + v0.y*v0.y + v0.z*v0.z + v0.w*v0.w
               + v1.x*v1.x + v1.y*v1.y + v1.z*v1.z + v1.w*v1.w;
        }
        for (int o = 16; o > 0; o >>= 1) ss += __shfl_xor_sync(0xffffffffu, ss, o);
        __shared__ float sW[8]; __shared__ float sInv;
        if ((tid & 31) == 0) sW[tid >> 5] = ss;
        __syncthreads();
        if (tid == 0) {
            float t = 0.f;
            for (int w = 0; w < 8; w++) t += sW[w];
            sInv = 1.0f / fmaxf(sqrtf(t), 1e-12f);
        }
        __syncthreads();
        if (tid < 96) {
            float inv = sInv;
            float v[8] = {v0.x*inv, v0.y*inv, v0.z*inv, v0.w*inv,
                          v1.x*inv, v1.y*inv, v1.z*inv, v1.w*inv};
            BF8 hi, lo;
#pragma unroll
            for (int j = 0; j < 8; j++) {
                hi.h[j] = __float2bfloat16(v[j]);
                lo.h[j] = __float2bfloat16(v[j] - __bfloat162float(hi.h[j]));
            }
            unsigned char* dst = g_Bb + (size_t)e * ROWB + tid * 16;
            *(uint4*)(dst)            = hi.u;   // hi segment
            *(uint4*)(dst + DD * 2)   = lo.u;   // lo segment
        }
        return;
    }

    if (blockIdx.x >= CC + BB) {
        // ---- anchor block: (b,c) from linear index ----
        int idx = blockIdx.x - (CC + BB);
        int b = idx >> 10, c = idx & 1023;
        if (targets[b * CC + c] == 0) return;      // uniform exit (~95% of blocks)

        __shared__ int sWi[8];
        __shared__ float sWf[4];
        __shared__ float sInv;
        int lane = tid & 31, wid = tid >> 5;

        // self-rank: count positives at columns < c (each thread: one int4)
        int e0 = tid * 4;
        int4 t4 = ((const int4*)(targets + b * CC))[tid];
        int r4 = (e0 < c && t4.x != 0) + (e0 + 1 < c && t4.y != 0)
               + (e0 + 2 < c && t4.z != 0) + (e0 + 3 < c && t4.w != 0);
        r4 = __reduce_add_sync(0xffffffffu, r4);
        if (lane == 0) sWi[wid] = r4;
        __syncthreads();
        int rank = sWi[0]+sWi[1]+sWi[2]+sWi[3]+sWi[4]+sWi[5]+sWi[6]+sWi[7];
        if (rank >= SLOTS_PER_B) return;
        int slot = b * SLOTS_PER_B + rank;

        // normalize f row (warps 0-2 load, block-wide reduce)
        const float4* src = (const float4*)(f + (size_t)(b * CC + c) * DD);
        float4 v0 = make_float4(0,0,0,0), v1 = make_float4(0,0,0,0);
        float ss = 0.f;
        if (tid < 96) {
            v0 = src[tid * 2]; v1 = src[tid * 2 + 1];
            ss = v0.x*v0.x + v0.y*v0.y + v0.z*v0.z + v0.w*v0.w
               + v1.x*v1.x + v1.y*v1.y + v1.z*v1.z + v1.w*v1.w;
        }
        for (int o = 16; o > 0; o >>= 1) ss += __shfl_xor_sync(0xffffffffu, ss, o);
        if ((tid & 31) == 0 && wid < 4) sWf[wid] = (wid < 3) ? ss : 0.f;
        __syncthreads();
        if (tid == 0) sInv = 1.0f / fmaxf(sqrtf(sWf[0] + sWf[1] + sWf[2]), 1e-12f);
        __syncthreads();
        if (tid >= 96) return;
        float inv = sInv;
        float v[8] = {v0.x*inv, v0.y*inv, v0.z*inv, v0.w*inv,
                      v1.x*inv, v1.y*inv, v1.z*inv, v1.w*inv};
        BF8 hi, lo;
#pragma unroll
        for (int j = 0; j < 8; j++) {
            hi.h[j] = __float2bfloat16(v[j]);
            lo.h[j] = __float2bfloat16(v[j] - __bfloat162float(hi.h[j]));
        }
        unsigned char* dst = g_Ab + (size_t)slot * ROWB + tid * 16;
        *(uint4*)(dst)            = hi.u;   // hi segment
        *(uint4*)(dst + DD * 2)   = lo.u;   // lo segment
        return;
    }

    // ---- per-batch compaction + exact random top-KRAND ----
    int b = blockIdx.x - CC;
    __shared__ unsigned int skey[CC];
    __shared__ unsigned char sfl[CC];
    __shared__ int hist[256];
    __shared__ int sW[8];
    __shared__ unsigned sWu[8];
    __shared__ int sQA[2];
    __shared__ int sOut;

    int lane = tid & 31, wid = tid >> 5;
    int e0 = tid * 4;
    unsigned int key[4]; int posf[4]; int cnt = 0;
#pragma unroll
    for (int j = 0; j < 4; j++) {
        int e = e0 + j;
        int isPos = (targets[b * CC + e] != 0);
        posf[j] = isPos; cnt += isPos;
        unsigned int k = isPos ? 0u : (__float_as_uint(rsc[b * CC + e]) + 1u);
        key[j] = k; skey[e] = k;
    }
    int inc = cnt;
    for (int o = 1; o < 32; o <<= 1) {
        int v = __shfl_up_sync(0xffffffffu, inc, o);
        if (lane >= o) inc += v;
    }
    if (lane == 31) sW[wid] = inc;
    __syncthreads();
    if (tid == 0) {
        int acc = 0;
        for (int w = 0; w < 8; w++) { int v = sW[w]; sW[w] = acc; acc += v; }
        g_posCount[b] = acc;
    }
    __syncthreads();
    int rank = sW[wid] + inc - cnt;
#pragma unroll
    for (int j = 0; j < 4; j++) {
        if (posf[j]) {
            if (rank < SLOTS_PER_B) g_posList[b * SLOTS_PER_B + rank] = e0 + j;
            rank++;
        }
    }

    // min (over negatives) / max of keys
    unsigned mk = max(max(key[0], key[1]), max(key[2], key[3]));
    unsigned nk0 = posf[0] ? 0xffffffffu : key[0];
    unsigned nk1 = posf[1] ? 0xffffffffu : key[1];
    unsigned nk2 = posf[2] ? 0xffffffffu : key[2];
    unsigned nk3 = posf[3] ? 0xffffffffu : key[3];
    unsigned nk = min(min(nk0, nk1), min(nk2, nk3));
    mk = __reduce_max_sync(0xffffffffu, mk);
    nk = __reduce_min_sync(0xffffffffu, nk);
    if (lane == 0) { sWu[wid] = mk; sW[wid] = (int)nk; }
    __syncthreads();
    unsigned mAll = sWu[0], nAll = (unsigned)sW[0];
#pragma unroll
    for (int w = 1; w < 8; w++) {
        mAll = max(mAll, sWu[w]);
        nAll = min(nAll, (unsigned)sW[w]);
    }

    // histogram descent to exact threshold (cell width 1); no trailing barrier
    unsigned lo = nAll;
    unsigned range = mAll - nAll + 1u;
    int above = 0;
    while (range > 1u) {
        unsigned step = range / 256u + 1u;
        hist[tid] = 0;
        __syncthreads();
#pragma unroll
        for (int j = 0; j < 4; j++) {
            unsigned d = key[j] - lo;            // wraps huge if key < lo
            if (d < range) atomicAdd(&hist[d / step], 1);
        }
        __syncthreads();
        if (wid == 0) {
            int h[8]; int ssum = 0;
            int base = lane * 8;
#pragma unroll
            for (int q = 0; q < 8; q++) { h[q] = hist[base + q]; ssum += h[q]; }
            int suf = ssum;
            for (int o = 1; o < 32; o <<= 1) {
                int v = __shfl_down_sync(0xffffffffu, suf, o);
                if (lane + o < 32) suf += v;
            }
            int hiAbove = above + suf - ssum;
            if (above + suf >= KRAND && hiAbove < KRAND) {   // exactly one lane
                int acc = hiAbove;
                int q = 7;
                for (; q > 0; q--) {
                    if (acc + h[q] >= KRAND) break;
                    acc += h[q];
                }
                sQA[0] = base + q;
                sQA[1] = acc;
            }
        }
        __syncthreads();
        lo = lo + (unsigned)sQA[0] * step;
        above = sQA[1];
        range = step;
    }
    unsigned V = lo;                              // exact KRAND-th largest key
    int n_gt = above;                             // exact count(key > V)
    int rrem = KRAND - n_gt;                      // ties needed at V (>=1)

    int ec = (key[0] == V) + (key[1] == V) + (key[2] == V) + (key[3] == V);
    ec = __reduce_add_sync(0xffffffffu, ec);
    if (lane == 0) sW[wid] = ec;
    __syncthreads();
    if (tid == 0) { int t = 0; for (int w = 0; w < 8; w++) t += sW[w]; sOut = t; }
    __syncthreads();
    int n_eq = sOut;

    if (n_eq == rrem) {
#pragma unroll
        for (int j = 0; j < 4; j++) sfl[e0 + j] = (key[j] >= V) ? 1 : 0;
        __syncthreads();
    } else {
#pragma unroll
        for (int j = 0; j < 4; j++) sfl[e0 + j] = (key[j] > V) ? 1 : 0;
        __syncthreads();
        if (tid == 0) {
            int rem = rrem;
            for (int e = 0; e < CC && rem > 0; e++)
                if (skey[e] == V) { sfl[e] = 1; rem--; }
        }
        __syncthreads();
    }
#pragma unroll
    for (int j = 0; j < 4; j++) g_randFlag[b * CC + e0 + j] = sfl[e0 + j];
}

// ---------------------------------------------------------------------------
// Kernel 1: bf16 tensor-core GEMM via mma.sync m16n8k16.
// 12 physical chunks; each loads 4 tiles (hiA,loA,hiB,loB) ONCE and runs
// 3 accumulate passes -> 98 MB L2 traffic. Grid (16, 8), 256 thr,
// 3-stage cp.async pipeline, 1 barrier/chunk.
// ---------------------------------------------------------------------------
__global__ void __launch_bounds__(256, 1) k_gemm_mma() {
    extern __shared__ __align__(16) unsigned char dynsm[];
    int m = blockIdx.x;
    int cnt = g_posCount[m]; if (cnt <= 0) return;
    if (cnt > SLOTS_PER_B) cnt = SLOTS_PER_B;
    int eBase = blockIdx.y * 128;

    int tid = threadIdx.x, lane = tid & 31, wid = tid >> 5;
    int wm = (wid & 1) * 64, wn = (wid >> 1) * 32;

    uint32_t sbase = smem_u32(dynsm);
    const unsigned char* gA = g_Ab + (size_t)m * 128 * ROWB;
    const unsigned char* gB = g_Bb + (size_t)eBase * ROWB;

    float acc[4][4][4];
#pragma unroll
    for (int i = 0; i < 4; i++)
#pragma unroll
        for (int j = 0; j < 4; j++)
#pragma unroll
            for (int q = 0; q < 4; q++) acc[i][j][q] = 0.f;

    auto copy_chunk = [&](int c, int st) {
        uint32_t sb = sbase + st * STAGE_BYTES;
        int hiOff = c * 128, loOff = (NPHYS + c) * 128;
#pragma unroll
        for (int i = 0; i < 4; i++) {
            int idx = tid + i * 256;
            int row = idx >> 3, seg = idx & 7;
            uint32_t so = (uint32_t)((row << 3) + (seg ^ (row & 7))) * 16;
            size_t rbA = (size_t)row * ROWB + seg * 16;
            cp16(sb + so,          gA + rbA + hiOff);   // hiA
            cp16(sb + TB + so,     gA + rbA + loOff);   // loA
            cp16(sb + 2*TB + so,   gB + rbA + hiOff);   // hiB
            cp16(sb + 3*TB + so,   gB + rbA + loOff);   // loB
        }
        asm volatile("cp.async.commit_group;" ::: "memory");
    };

    copy_chunk(0, 0);
    copy_chunk(1, 1);

    for (int c = 0; c < NPHYS; c++) {
        if (c + 1 < NPHYS)
            asm volatile("cp.async.wait_group 1;" ::: "memory");
        else
            asm volatile("cp.async.wait_group 0;" ::: "memory");
        __syncthreads();
        if (c + 2 < NPHYS) copy_chunk(c + 2, (c + 2) % 3);

        uint32_t sb = sbase + (c % 3) * STAGE_BYTES;
        uint32_t sHiA = sb, sLoA = sb + TB, sHiB = sb + 2*TB, sLoB = sb + 3*TB;
#pragma unroll
        for (int ks = 0; ks < 4; ks++) {
            uint32_t aH[4][4], aL[4][4], bH[4][2], bL[4][2];
#pragma unroll
            for (int mi = 0; mi < 4; mi++) {
                int row = wm + mi * 16 + (lane & 15);
                int kseg = 2 * ks + (lane >> 4);
                uint32_t off = (uint32_t)((row << 3) + (kseg ^ (row & 7))) * 16;
                ldsm_x4(aH[mi][0], aH[mi][1], aH[mi][2], aH[mi][3], sHiA + off);
                ldsm_x4(aL[mi][0], aL[mi][1], aL[mi][2], aL[mi][3], sLoA + off);
            }
#pragma unroll
            for (int ni = 0; ni < 4; ni++) {
                int rn = wn + ni * 8 + (lane & 7);
                int kseg = 2 * ks + ((lane >> 3) & 1);
                uint32_t off = (uint32_t)((rn << 3) + (kseg ^ (rn & 7))) * 16;
                ldsm_x2(bH[ni][0], bH[ni][1], sHiB + off);
                ldsm_x2(bL[ni][0], bL[ni][1], sLoB + off);
            }
#pragma unroll
            for (int mi = 0; mi < 4; mi++)
#pragma unroll
                for (int ni = 0; ni < 4; ni++) {
                    mma16816(acc[mi][ni], aH[mi], bH[ni]);   // hi.hi
                    mma16816(acc[mi][ni], aH[mi], bL[ni]);   // hi.lo
                    mma16816(acc[mi][ni], aL[mi], bH[ni]);   // lo.hi
                }
        }
    }

    int qr = lane >> 2, qc = (lane & 3) * 2;
#pragma unroll
    for (int mi = 0; mi < 4; mi++) {
#pragma unroll
        for (int ni = 0; ni < 4; ni++) {
            int r0 = wm + mi * 16 + qr;
            int col = eBase + wn + ni * 8 + qc;
            if (r0 < cnt)
                *(float2*)(g_S + (size_t)(m * 128 + r0) * CC + col)
                    = make_float2(acc[mi][ni][0], acc[mi][ni][1]);
            if (r0 + 8 < cnt)
                *(float2*)(g_S + (size_t)(m * 128 + r0 + 8) * CC + col)
                    = make_float2(acc[mi][ni][2], acc[mi][ni][3]);
        }
    }
}

// ---------------------------------------------------------------------------
// Kernel 2: per positive anchor: top-KHARD exp-sum via 3-pass 256-bin
// histogram descent + random-set exp sum -> loss term.
// ---------------------------------------------------------------------------
__global__ void k_select(const int* __restrict__ targets) {
    int i = blockIdx.x;
    int b = i >> 7, r = i & 127;
    int cnt = g_posCount[b]; if (cnt > SLOTS_PER_B) cnt = SLOTS_PER_B;
    int tid = threadIdx.x;
    if (r >= cnt) { if (tid == 0) g_term[i] = 0.f; return; }
    int c = g_posList[i];

    __shared__ int hist[256];
    __shared__ unsigned sWmax[8];
    __shared__ unsigned sWmin[8];
    __shared__ int sQA[2];
    __shared__ float sWf[8];

    int lane = tid & 31, wid = tid >> 5;

    float4 sa = *((const float4*)(g_S + (size_t)i * CC) + tid);
    int4   t4 = *((const int4*)(targets + b * CC) + tid);
    uchar4 r4 = *((const uchar4*)(g_randFlag + b * CC) + tid);
    float s[4] = {sa.x, sa.y, sa.z, sa.w};
    int neg[4] = {t4.x == 0, t4.y == 0, t4.z == 0, t4.w == 0};
    int fl[4]  = {r4.x, r4.y, r4.z, r4.w};
    unsigned key[4];
#pragma unroll
    for (int j = 0; j < 4; j++) key[j] = neg[j] ? fkey(s[j]) : 0u;

    unsigned mk = max(max(key[0], key[1]), max(key[2], key[3]));
    unsigned nk0 = neg[0] ? key[0] : 0xffffffffu;
    unsigned nk1 = neg[1] ? key[1] : 0xffffffffu;
    unsigned nk2 = neg[2] ? key[2] : 0xffffffffu;
    unsigned nk3 = neg[3] ? key[3] : 0xffffffffu;
    unsigned nk = min(min(nk0, nk1), min(nk2, nk3));
    mk = __reduce_max_sync(0xffffffffu, mk);
    nk = __reduce_min_sync(0xffffffffu, nk);
    if (lane == 0) { sWmax[wid] = mk; sWmin[wid] = nk; }
    __syncthreads();
    unsigned mAll = sWmax[0], nAll = sWmin[0];
#pragma unroll
    for (int w = 1; w < 8; w++) { mAll = max(mAll, sWmax[w]); nAll = min(nAll, sWmin[w]); }
    float M = funkey(mAll);

    // 3-pass histogram descent; no trailing barrier
    unsigned lo = nAll;
    unsigned range = mAll - nAll + 1u;
    unsigned step = 1u;
    int above = 0;
#pragma unroll
    for (int pass = 0; pass < 3; pass++) {
        step = range / 256u + 1u;
        hist[tid] = 0;
        __syncthreads();
#pragma unroll
        for (int j = 0; j < 4; j++) {
            unsigned d = key[j] - lo;            // wraps huge if key < lo
            if (d < range) atomicAdd(&hist[d / step], 1);
        }
        __syncthreads();
        if (wid == 0) {
            int h[8]; int ssum = 0;
            int base = lane * 8;
#pragma unroll
            for (int q = 0; q < 8; q++) { h[q] = hist[base + q]; ssum += h[q]; }
            int suf = ssum;
            for (int o = 1; o < 32; o <<= 1) {
                int v = __shfl_down_sync(0xffffffffu, suf, o);
                if (lane + o < 32) suf += v;
            }
            int hiAbove = above + suf - ssum;
            if (above + suf >= KHARD && hiAbove < KHARD) {   // exactly one lane
                int acc = hiAbove;
                int q = 7;
                for (; q > 0; q--) {
                    if (acc + h[q] >= KHARD) break;
                    acc += h[q];
                }
                sQA[0] = base + q;
                sQA[1] = acc;
            }
        }
        __syncthreads();
        int Q = sQA[0]; above = sQA[1];
        lo = lo + (unsigned)Q * step;
        range = step;
    }
    unsigned Hi = lo + step;
    int rem = KHARD - above;                     // >= 1 ties in [lo, Hi)

    float es = 0.f;
#pragma unroll
    for (int j = 0; j < 4; j++) {
        float e = __expf((s[j] - M) * TAU_INV);
        if (key[j] >= Hi) es += e;
        if (fl[j])        es += e;
    }
    for (int o = 16; o > 0; o >>= 1) es += __shfl_xor_sync(0xffffffffu, es, o);
    if (lane == 0) sWf[wid] = es;
    __syncthreads();

    if (tid == 0) {
        float su = sWf[0]+sWf[1]+sWf[2]+sWf[3]+sWf[4]+sWf[5]+sWf[6]+sWf[7];
        su += (float)rem * __expf((funkey(lo) - M) * TAU_INV);
        float pos = g_S[(size_t)i * CC + c] * TAU_INV;
        float lse = M * TAU_INV + __logf(su);
        float d = lse - pos;
        float term = (d > 0.f) ? d + log1pf(__expf(-d)) : log1pf(__expf(d));
        g_term[i] = term;
    }
}

// ---------------------------------------------------------------------------
// Kernel 3: deterministic final reduction -> scalar loss
// ---------------------------------------------------------------------------
__global__ void k_final(float* __restrict__ out) {
    __shared__ float sbs[BB];
    int wid = threadIdx.x >> 5, lane = threadIdx.x & 31;
    float s = 0.f;
    for (int r = lane; r < SLOTS_PER_B; r += 32) s += g_term[wid * SLOTS_PER_B + r];
    for (int o = 16; o > 0; o >>= 1) s += __shfl_xor_sync(0xffffffffu, s, o);
    if (lane == 0) sbs[wid] = s;
    __syncthreads();
    if (threadIdx.x == 0) {
        float tot = 0.f;
        for (int b = 0; b < BB; b++) {
            int pc = g_posCount[b]; if (pc < 1) pc = 1;
            tot += sbs[b] / (float)pc;
        }
        out[0] = tot / (float)BB;
    }
}

extern "C" void kernel_launch(void* const* d_in, const int* in_sizes, int n_in,
                              void* d_out, int out_size) {
    const float* f       = (const float*)d_in[0];   // (B,C,D)
    const float* p       = (const float*)d_in[1];   // (C,D)
    const int*   targets = (const int*)  d_in[2];   // (B,C)
    const float* rsc     = (const float*)d_in[3];   // (B,C)
    float* out = (float*)d_out;

    cudaFuncSetAttribute(k_gemm_mma, cudaFuncAttributeMaxDynamicSharedMemorySize, DYN_SMEM);

    k_prep<<<CC + BB + BB * CC, 256>>>(p, f, targets, rsc);
    k_gemm_mma<<<dim3(BB, CC / 128), 256, DYN_SMEM>>>();
    k_select<<<MAXP, 256>>>(targets);
    k_final<<<1, 512>>>(out);
}

// round 16
// speedup vs baseline: 1.0286x; 1.0286x over previous
#include <cuda_runtime.h>
#include <cuda_bf16.h>
#include <math.h>
#include <stdint.h>

// Problem constants
#define BB 16
#define CC 1024
#define DD 768
#define TAU_INV 10.0f
#define KHARD 306
#define KRAND 717
#define SLOTS_PER_B 128
#define MAXP (BB * SLOTS_PER_B)   // 2048

// Split-bf16: rows stored as [hi|lo], K=1536 bf16 = 3072 B/row.
#define ROWB 3072
#define NPHYS 12
#define TB 16384                  // one 128x128B tile
#define STAGE_BYTES (4 * TB)      // 64 KB: hiA loA hiB loB
#define NSTAGE 3
#define DYN_SMEM (NSTAGE * STAGE_BYTES)   // 192 KB

// Static device scratch (zero-init at load; unused slot rows never written)
__device__ __align__(128) unsigned char g_Ab[(size_t)MAXP * ROWB];   // 6.3 MB
__device__ __align__(128) unsigned char g_Bb[(size_t)CC * ROWB];     // 3.1 MB
__device__ float g_S[(size_t)MAXP * CC];
__device__ int   g_posList[MAXP];
__device__ int   g_posCount[BB];
__device__ unsigned char g_randFlag[BB * CC];
__device__ float g_term[MAXP];

// ---------------------------------------------------------------------------
// helpers
// ---------------------------------------------------------------------------
__device__ __forceinline__ uint32_t smem_u32(const void* p) {
    uint32_t a;
    asm("{ .reg .u64 t; cvta.to.shared.u64 t, %1; cvt.u32.u64 %0, t; }" : "=r"(a) : "l"(p));
    return a;
}
__device__ __forceinline__ void cp16(uint32_t dst, const void* src) {
    asm volatile("cp.async.ca.shared.global [%0], [%1], 16;" :: "r"(dst), "l"(src) : "memory");
}
__device__ __forceinline__ void ldsm_x4(uint32_t& r0, uint32_t& r1, uint32_t& r2, uint32_t& r3,
                                        uint32_t a) {
    asm volatile("ldmatrix.sync.aligned.m8n8.x4.shared.b16 {%0,%1,%2,%3}, [%4];"
                 : "=r"(r0), "=r"(r1), "=r"(r2), "=r"(r3) : "r"(a));
}
__device__ __forceinline__ void ldsm_x2(uint32_t& r0, uint32_t& r1, uint32_t a) {
    asm volatile("ldmatrix.sync.aligned.m8n8.x2.shared.b16 {%0,%1}, [%2];"
                 : "=r"(r0), "=r"(r1) : "r"(a));
}
__device__ __forceinline__ void mma16816(float* c, const uint32_t* a, const uint32_t* b) {
    asm volatile("mma.sync.aligned.m16n8k16.row.col.f32.bf16.bf16.f32 "
                 "{%0,%1,%2,%3}, {%4,%5,%6,%7}, {%8,%9}, {%0,%1,%2,%3};"
                 : "+f"(c[0]), "+f"(c[1]), "+f"(c[2]), "+f"(c[3])
                 : "r"(a[0]), "r"(a[1]), "r"(a[2]), "r"(a[3]), "r"(b[0]), "r"(b[1]));
}
// order-preserving float<->uint key
__device__ __forceinline__ unsigned fkey(float f) {
    unsigned u = __float_as_uint(f);
    return (u & 0x80000000u) ? ~u : (u | 0x80000000u);
}
__device__ __forceinline__ float funkey(unsigned u) {
    return __uint_as_float((u & 0x80000000u) ? (u & 0x7fffffffu) : ~u);
}

union BF8 { __nv_bfloat16 h[8]; uint4 u; };

// ---------------------------------------------------------------------------
// Kernel 0 (fused): blocks [0,CC): normalize proto row, split bf16, write
// g_Bb row [hi|lo]. Blocks [CC,CC+BB): compaction + exact random top-KRAND
// via histogram descent run to step==1.
// ---------------------------------------------------------------------------
__global__ void k_prep(const float* __restrict__ p,
                       const int* __restrict__ targets,
                       const float* __restrict__ rsc) {
    int tid = threadIdx.x;
    if (blockIdx.x < CC) {
        int e = blockIdx.x;
        const float4* row = (const float4*)(p + (size_t)e * DD);
        float4 v0 = make_float4(0,0,0,0), v1 = make_float4(0,0,0,0);
        float ss = 0.f;
        if (tid < 96) {
            v0 = row[tid * 2]; v1 = row[tid * 2 + 1];
            ss = v0.x*v0.x + v0.y*v0.y + v0.z*v0.z + v0.w*v0.w
               + v1.x*v1.x + v1.y*v1.y + v1.z*v1.z + v1.w*v1.w;
        }
        for (int o = 16; o > 0; o >>= 1) ss += __shfl_xor_sync(0xffffffffu, ss, o);
        __shared__ float sW[8]; __shared__ float sInv;
        if ((tid & 31) == 0) sW[tid >> 5] = ss;
        __syncthreads();
        if (tid == 0) {
            float t = 0.f;
            for (int w = 0; w < 8; w++) t += sW[w];
            sInv = 1.0f / fmaxf(sqrtf(t), 1e-12f);
        }
        __syncthreads();
        if (tid < 96) {
            float inv = sInv;
            float v[8] = {v0.x*inv, v0.y*inv, v0.z*inv, v0.w*inv,
                          v1.x*inv, v1.y*inv, v1.z*inv, v1.w*inv};
            BF8 hi, lo;
#pragma unroll
            for (int j = 0; j < 8; j++) {
                hi.h[j] = __float2bfloat16(v[j]);
                lo.h[j] = __float2bfloat16(v[j] - __bfloat162float(hi.h[j]));
            }
            unsigned char* dst = g_Bb + (size_t)e * ROWB + tid * 16;
            *(uint4*)(dst)            = hi.u;   // hi segment
            *(uint4*)(dst + DD * 2)   = lo.u;   // lo segment
        }
        return;
    }

    // ---- per-batch compaction + exact random top-KRAND ----
    int b = blockIdx.x - CC;
    __shared__ unsigned int skey[CC];
    __shared__ unsigned char sfl[CC];
    __shared__ int hist[256];
    __shared__ int sW[8];
    __shared__ unsigned sWu[8];
    __shared__ int sQA[2];
    __shared__ int sOut;

    int lane = tid & 31, wid = tid >> 5;
    int e0 = tid * 4;
    unsigned int key[4]; int posf[4]; int cnt = 0;
#pragma unroll
    for (int j = 0; j < 4; j++) {
        int e = e0 + j;
        int isPos = (targets[b * CC + e] != 0);
        posf[j] = isPos; cnt += isPos;
        unsigned int k = isPos ? 0u : (__float_as_uint(rsc[b * CC + e]) + 1u);
        key[j] = k; skey[e] = k;
    }
    int inc = cnt;
    for (int o = 1; o < 32; o <<= 1) {
        int v = __shfl_up_sync(0xffffffffu, inc, o);
        if (lane >= o) inc += v;
    }
    if (lane == 31) sW[wid] = inc;
    __syncthreads();
    if (tid == 0) {
        int acc = 0;
        for (int w = 0; w < 8; w++) { int v = sW[w]; sW[w] = acc; acc += v; }
        g_posCount[b] = acc;
    }
    __syncthreads();
    int rank = sW[wid] + inc - cnt;
#pragma unroll
    for (int j = 0; j < 4; j++) {
        if (posf[j]) {
            if (rank < SLOTS_PER_B) g_posList[b * SLOTS_PER_B + rank] = e0 + j;
            rank++;
        }
    }

    unsigned mk = max(max(key[0], key[1]), max(key[2], key[3]));
    unsigned nk0 = posf[0] ? 0xffffffffu : key[0];
    unsigned nk1 = posf[1] ? 0xffffffffu : key[1];
    unsigned nk2 = posf[2] ? 0xffffffffu : key[2];
    unsigned nk3 = posf[3] ? 0xffffffffu : key[3];
    unsigned nk = min(min(nk0, nk1), min(nk2, nk3));
    mk = __reduce_max_sync(0xffffffffu, mk);
    nk = __reduce_min_sync(0xffffffffu, nk);
    if (lane == 0) { sWu[wid] = mk; sW[wid] = (int)nk; }
    __syncthreads();
    unsigned mAll = sWu[0], nAll = (unsigned)sW[0];
#pragma unroll
    for (int w = 1; w < 8; w++) {
        mAll = max(mAll, sWu[w]);
        nAll = min(nAll, (unsigned)sW[w]);
    }

    // histogram descent to exact threshold (cell width 1); no trailing barrier
    unsigned lo = nAll;
    unsigned range = mAll - nAll + 1u;
    int above = 0;
    while (range > 1u) {
        unsigned step = range / 256u + 1u;
        hist[tid] = 0;
        __syncthreads();
#pragma unroll
        for (int j = 0; j < 4; j++) {
            unsigned d = key[j] - lo;            // wraps huge if key < lo
            if (d < range) atomicAdd(&hist[d / step], 1);
        }
        __syncthreads();
        if (wid == 0) {
            int h[8]; int ssum = 0;
            int base = lane * 8;
#pragma unroll
            for (int q = 0; q < 8; q++) { h[q] = hist[base + q]; ssum += h[q]; }
            int suf = ssum;
            for (int o = 1; o < 32; o <<= 1) {
                int v = __shfl_down_sync(0xffffffffu, suf, o);
                if (lane + o < 32) suf += v;
            }
            int hiAbove = above + suf - ssum;
            if (above + suf >= KRAND && hiAbove < KRAND) {   // exactly one lane
                int acc = hiAbove;
                int q = 7;
                for (; q > 0; q--) {
                    if (acc + h[q] >= KRAND) break;
                    acc += h[q];
                }
                sQA[0] = base + q;
                sQA[1] = acc;
            }
        }
        __syncthreads();
        lo = lo + (unsigned)sQA[0] * step;
        above = sQA[1];
        range = step;
    }
    unsigned V = lo;                              // exact KRAND-th largest key
    int n_gt = above;
    int rrem = KRAND - n_gt;

    int ec = (key[0] == V) + (key[1] == V) + (key[2] == V) + (key[3] == V);
    ec = __reduce_add_sync(0xffffffffu, ec);
    if (lane == 0) sW[wid] = ec;
    __syncthreads();
    if (tid == 0) { int t = 0; for (int w = 0; w < 8; w++) t += sW[w]; sOut = t; }
    __syncthreads();
    int n_eq = sOut;

    if (n_eq == rrem) {
#pragma unroll
        for (int j = 0; j < 4; j++) sfl[e0 + j] = (key[j] >= V) ? 1 : 0;
        __syncthreads();
    } else {
#pragma unroll
        for (int j = 0; j < 4; j++) sfl[e0 + j] = (key[j] > V) ? 1 : 0;
        __syncthreads();
        if (tid == 0) {
            int rem = rrem;
            for (int e = 0; e < CC && rem > 0; e++)
                if (skey[e] == V) { sfl[e] = 1; rem--; }
        }
        __syncthreads();
    }
#pragma unroll
    for (int j = 0; j < 4; j++) g_randFlag[b * CC + e0 + j] = sfl[e0 + j];
}

// ---------------------------------------------------------------------------
// Kernel 1: gather + normalize positive anchor rows, split bf16, write
// g_Ab row [hi|lo].
// ---------------------------------------------------------------------------
__global__ void k_norm_f(const float* __restrict__ f) {
    int i = blockIdx.x;
    int b = i >> 7, r = i & 127;
    int cnt = g_posCount[b]; if (cnt > SLOTS_PER_B) cnt = SLOTS_PER_B;
    if (r >= cnt) return;
    int c = g_posList[i];
    int tid = threadIdx.x;

    const float4* src = (const float4*)(f + (size_t)(b * CC + c) * DD);
    float4 v0 = make_float4(0,0,0,0), v1 = make_float4(0,0,0,0);
    float ss = 0.f;
    if (tid < 96) {
        v0 = src[tid * 2]; v1 = src[tid * 2 + 1];
        ss = v0.x*v0.x + v0.y*v0.y + v0.z*v0.z + v0.w*v0.w
           + v1.x*v1.x + v1.y*v1.y + v1.z*v1.z + v1.w*v1.w;
    }
    for (int o = 16; o > 0; o >>= 1) ss += __shfl_xor_sync(0xffffffffu, ss, o);
    __shared__ float sW[4]; __shared__ float sInv;
    if ((tid & 31) == 0) sW[tid >> 5] = ss;
    __syncthreads();
    if (tid == 0) sInv = 1.0f / fmaxf(sqrtf(sW[0]+sW[1]+sW[2]+sW[3]), 1e-12f);
    __syncthreads();
    if (tid >= 96) return;
    float inv = sInv;
    float v[8] = {v0.x*inv, v0.y*inv, v0.z*inv, v0.w*inv,
                  v1.x*inv, v1.y*inv, v1.z*inv, v1.w*inv};
    BF8 hi, lo;
#pragma unroll
    for (int j = 0; j < 8; j++) {
        hi.h[j] = __float2bfloat16(v[j]);
        lo.h[j] = __float2bfloat16(v[j] - __bfloat162float(hi.h[j]));
    }
    unsigned char* dst = g_Ab + (size_t)i * ROWB + tid * 16;
    *(uint4*)(dst)            = hi.u;   // hi segment
    *(uint4*)(dst + DD * 2)   = lo.u;   // lo segment
}

// ---------------------------------------------------------------------------
// Kernel 2: bf16 tensor-core GEMM via mma.sync m16n8k16 (R14-verified).
// ---------------------------------------------------------------------------
__global__ void __launch_bounds__(256, 1) k_gemm_mma() {
    extern __shared__ __align__(16) unsigned char dynsm[];
    int m = blockIdx.x;
    int cnt = g_posCount[m]; if (cnt <= 0) return;
    if (cnt > SLOTS_PER_B) cnt = SLOTS_PER_B;
    int eBase = blockIdx.y * 128;

    int tid = threadIdx.x, lane = tid & 31, wid = tid >> 5;
    int wm = (wid & 1) * 64, wn = (wid >> 1) * 32;

    uint32_t sbase = smem_u32(dynsm);
    const unsigned char* gA = g_Ab + (size_t)m * 128 * ROWB;
    const unsigned char* gB = g_Bb + (size_t)eBase * ROWB;

    float acc[4][4][4];
#pragma unroll
    for (int i = 0; i < 4; i++)
#pragma unroll
        for (int j = 0; j < 4; j++)
#pragma unroll
            for (int q = 0; q < 4; q++) acc[i][j][q] = 0.f;

    auto copy_chunk = [&](int c, int st) {
        uint32_t sb = sbase + st * STAGE_BYTES;
        int hiOff = c * 128, loOff = (NPHYS + c) * 128;
#pragma unroll
        for (int i = 0; i < 4; i++) {
            int idx = tid + i * 256;
            int row = idx >> 3, seg = idx & 7;
            uint32_t so = (uint32_t)((row << 3) + (seg ^ (row & 7))) * 16;
            size_t rbA = (size_t)row * ROWB + seg * 16;
            cp16(sb + so,          gA + rbA + hiOff);   // hiA
            cp16(sb + TB + so,     gA + rbA + loOff);   // loA
            cp16(sb + 2*TB + so,   gB + rbA + hiOff);   // hiB
            cp16(sb + 3*TB + so,   gB + rbA + loOff);   // loB
        }
        asm volatile("cp.async.commit_group;" ::: "memory");
    };

    copy_chunk(0, 0);
    copy_chunk(1, 1);

    for (int c = 0; c < NPHYS; c++) {
        if (c + 1 < NPHYS)
            asm volatile("cp.async.wait_group 1;" ::: "memory");
        else
            asm volatile("cp.async.wait_group 0;" ::: "memory");
        __syncthreads();
        if (c + 2 < NPHYS) copy_chunk(c + 2, (c + 2) % 3);

        uint32_t sb = sbase + (c % 3) * STAGE_BYTES;
        uint32_t sHiA = sb, sLoA = sb + TB, sHiB = sb + 2*TB, sLoB = sb + 3*TB;
#pragma unroll
        for (int ks = 0; ks < 4; ks++) {
            uint32_t aH[4][4], aL[4][4], bH[4][2], bL[4][2];
#pragma unroll
            for (int mi = 0; mi < 4; mi++) {
                int row = wm + mi * 16 + (lane & 15);
                int kseg = 2 * ks + (lane >> 4);
                uint32_t off = (uint32_t)((row << 3) + (kseg ^ (row & 7))) * 16;
                ldsm_x4(aH[mi][0], aH[mi][1], aH[mi][2], aH[mi][3], sHiA + off);
                ldsm_x4(aL[mi][0], aL[mi][1], aL[mi][2], aL[mi][3], sLoA + off);
            }
#pragma unroll
            for (int ni = 0; ni < 4; ni++) {
                int rn = wn + ni * 8 + (lane & 7);
                int kseg = 2 * ks + ((lane >> 3) & 1);
                uint32_t off = (uint32_t)((rn << 3) + (kseg ^ (rn & 7))) * 16;
                ldsm_x2(bH[ni][0], bH[ni][1], sHiB + off);
                ldsm_x2(bL[ni][0], bL[ni][1], sLoB + off);
            }
#pragma unroll
            for (int mi = 0; mi < 4; mi++)
#pragma unroll
                for (int ni = 0; ni < 4; ni++) {
                    mma16816(acc[mi][ni], aH[mi], bH[ni]);   // hi.hi
                    mma16816(acc[mi][ni], aH[mi], bL[ni]);   // hi.lo
                    mma16816(acc[mi][ni], aL[mi], bH[ni]);   // lo.hi
                }
        }
    }

    int qr = lane >> 2, qc = (lane & 3) * 2;
#pragma unroll
    for (int mi = 0; mi < 4; mi++) {
#pragma unroll
        for (int ni = 0; ni < 4; ni++) {
            int r0 = wm + mi * 16 + qr;
            int col = eBase + wn + ni * 8 + qc;
            if (r0 < cnt)
                *(float2*)(g_S + (size_t)(m * 128 + r0) * CC + col)
                    = make_float2(acc[mi][ni][0], acc[mi][ni][1]);
            if (r0 + 8 < cnt)
                *(float2*)(g_S + (size_t)(m * 128 + r0 + 8) * CC + col)
                    = make_float2(acc[mi][ni][2], acc[mi][ni][3]);
        }
    }
}

// ---------------------------------------------------------------------------
// Kernel 3: PAIRED select — one block handles slots 2*bid and 2*bid+1
// (always same batch: 128 slots/batch is even). Shares all barriers and the
// targets/randFlag loads between the two histogram descents.
// ---------------------------------------------------------------------------
__global__ void k_select(const int* __restrict__ targets) {
    int i0 = blockIdx.x * 2, i1 = i0 + 1;
    int b = i0 >> 7, r0 = i0 & 127;
    int cnt = g_posCount[b]; if (cnt > SLOTS_PER_B) cnt = SLOTS_PER_B;
    int tid = threadIdx.x;
    bool v0 = (r0 < cnt), v1 = (r0 + 1 < cnt);
    if (!v0) {                                   // v0 false implies v1 false
        if (tid == 0) { g_term[i0] = 0.f; g_term[i1] = 0.f; }
        return;
    }
    if (tid == 0 && !v1) g_term[i1] = 0.f;

    __shared__ int hist[2][256];
    __shared__ unsigned sWmax[2][8];
    __shared__ unsigned sWmin[2][8];
    __shared__ int sQA[2][2];
    __shared__ float sWf[2][8];

    int lane = tid & 31, wid = tid >> 5;

    int c0 = g_posList[i0];
    int c1 = v1 ? g_posList[i1] : 0;
    float4 sa = *((const float4*)(g_S + (size_t)i0 * CC) + tid);
    float4 sb = v1 ? *((const float4*)(g_S + (size_t)i1 * CC) + tid)
                   : make_float4(0,0,0,0);
    int4   t4 = *((const int4*)(targets + b * CC) + tid);
    uchar4 rf = *((const uchar4*)(g_randFlag + b * CC) + tid);
    float s0[4] = {sa.x, sa.y, sa.z, sa.w};
    float s1[4] = {sb.x, sb.y, sb.z, sb.w};
    int neg[4] = {t4.x == 0, t4.y == 0, t4.z == 0, t4.w == 0};
    int fl[4]  = {rf.x, rf.y, rf.z, rf.w};
    unsigned k0[4], k1[4];
#pragma unroll
    for (int j = 0; j < 4; j++) {
        k0[j] = neg[j] ? fkey(s0[j]) : 0u;
        k1[j] = (v1 && neg[j]) ? fkey(s1[j]) : 0u;
    }

    // per-search max / min-over-negatives (search1 degenerates harmlessly)
#pragma unroll
    for (int t = 0; t < 2; t++) {
        const unsigned* k = t ? k1 : k0;
        unsigned mk = max(max(k[0], k[1]), max(k[2], k[3]));
        unsigned a0 = neg[0] ? k[0] : 0xffffffffu;
        unsigned a1 = neg[1] ? k[1] : 0xffffffffu;
        unsigned a2 = neg[2] ? k[2] : 0xffffffffu;
        unsigned a3 = neg[3] ? k[3] : 0xffffffffu;
        unsigned nk = min(min(a0, a1), min(a2, a3));
        mk = __reduce_max_sync(0xffffffffu, mk);
        nk = __reduce_min_sync(0xffffffffu, nk);
        if (lane == 0) { sWmax[t][wid] = mk; sWmin[t][wid] = nk; }
    }
    __syncthreads();
    unsigned mA[2], nA[2];
#pragma unroll
    for (int t = 0; t < 2; t++) {
        unsigned m = sWmax[t][0], n = sWmin[t][0];
#pragma unroll
        for (int w = 1; w < 8; w++) { m = max(m, sWmax[t][w]); n = min(n, sWmin[t][w]); }
        mA[t] = m; nA[t] = n;
    }
    float M0 = funkey(mA[0]);
    float M1 = funkey(mA[1]);

    // dual 3-pass histogram descent sharing barriers
    unsigned lo[2]  = {nA[0], nA[1]};
    unsigned rng[2] = {mA[0] - nA[0] + 1u, mA[1] - nA[1] + 1u};
    unsigned stp[2] = {1u, 1u};
    int abv[2] = {0, 0};
#pragma unroll
    for (int pass = 0; pass < 3; pass++) {
        stp[0] = rng[0] / 256u + 1u;
        stp[1] = rng[1] / 256u + 1u;
        hist[0][tid] = 0; hist[1][tid] = 0;
        __syncthreads();
#pragma unroll
        for (int j = 0; j < 4; j++) {
            unsigned d0 = k0[j] - lo[0];
            if (d0 < rng[0]) atomicAdd(&hist[0][d0 / stp[0]], 1);
            unsigned d1 = k1[j] - lo[1];
            if (d1 < rng[1]) atomicAdd(&hist[1][d1 / stp[1]], 1);
        }
        __syncthreads();
        if (wid == 0) {
#pragma unroll
            for (int t = 0; t < 2; t++) {
                int h[8]; int ssum = 0;
                int base = lane * 8;
#pragma unroll
                for (int q = 0; q < 8; q++) { h[q] = hist[t][base + q]; ssum += h[q]; }
                int suf = ssum;
                for (int o = 1; o < 32; o <<= 1) {
                    int v = __shfl_down_sync(0xffffffffu, suf, o);
                    if (lane + o < 32) suf += v;
                }
                int hiAbove = abv[t] + suf - ssum;
                if (abv[t] + suf >= KHARD && hiAbove < KHARD) {   // one lane
                    int acc = hiAbove;
                    int q = 7;
                    for (; q > 0; q--) {
                        if (acc + h[q] >= KHARD) break;
                        acc += h[q];
                    }
                    sQA[t][0] = base + q;
                    sQA[t][1] = acc;
                }
            }
        }
        __syncthreads();
#pragma unroll
        for (int t = 0; t < 2; t++) {
            lo[t] = lo[t] + (unsigned)sQA[t][0] * stp[t];
            abv[t] = sQA[t][1];
            rng[t] = stp[t];
        }
    }
    unsigned Hi0 = lo[0] + stp[0], Hi1 = lo[1] + stp[1];
    int rem0 = KHARD - abv[0], rem1 = KHARD - abv[1];

    float es0 = 0.f, es1 = 0.f;
#pragma unroll
    for (int j = 0; j < 4; j++) {
        float e0 = __expf((s0[j] - M0) * TAU_INV);
        if (k0[j] >= Hi0) es0 += e0;
        if (fl[j])        es0 += e0;
        float e1 = __expf((s1[j] - M1) * TAU_INV);
        if (k1[j] >= Hi1) es1 += e1;
        if (fl[j])        es1 += e1;
    }
    for (int o = 16; o > 0; o >>= 1) {
        es0 += __shfl_xor_sync(0xffffffffu, es0, o);
        es1 += __shfl_xor_sync(0xffffffffu, es1, o);
    }
    if (lane == 0) { sWf[0][wid] = es0; sWf[1][wid] = es1; }
    __syncthreads();

    if (tid == 0) {
        float su0 = 0.f, su1 = 0.f;
#pragma unroll
        for (int w = 0; w < 8; w++) { su0 += sWf[0][w]; su1 += sWf[1][w]; }
        su0 += (float)rem0 * __expf((funkey(lo[0]) - M0) * TAU_INV);
        float pos0 = g_S[(size_t)i0 * CC + c0] * TAU_INV;
        float lse0 = M0 * TAU_INV + __logf(su0);
        float d0 = lse0 - pos0;
        g_term[i0] = (d0 > 0.f) ? d0 + log1pf(__expf(-d0)) : log1pf(__expf(d0));
        if (v1) {
            su1 += (float)rem1 * __expf((funkey(lo[1]) - M1) * TAU_INV);
            float pos1 = g_S[(size_t)i1 * CC + c1] * TAU_INV;
            float lse1 = M1 * TAU_INV + __logf(su1);
            float d1 = lse1 - pos1;
            g_term[i1] = (d1 > 0.f) ? d1 + log1pf(__expf(-d1)) : log1pf(__expf(d1));
        }
    }
}

// ---------------------------------------------------------------------------
// Kernel 4: deterministic final reduction -> scalar loss
// ---------------------------------------------------------------------------
__global__ void k_final(float* __restrict__ out) {
    __shared__ float sbs[BB];
    int wid = threadIdx.x >> 5, lane = threadIdx.x & 31;
    float s = 0.f;
    for (int r = lane; r < SLOTS_PER_B; r += 32) s += g_term[wid * SLOTS_PER_B + r];
    for (int o = 16; o > 0; o >>= 1) s += __shfl_xor_sync(0xffffffffu, s, o);
    if (lane == 0) sbs[wid] = s;
    __syncthreads();
    if (threadIdx.x == 0) {
        float tot = 0.f;
        for (int b = 0; b < BB; b++) {
            int pc = g_posCount[b]; if (pc < 1) pc = 1;
            tot += sbs[b] / (float)pc;
        }
        out[0] = tot / (float)BB;
    }
}

extern "C" void kernel_launch(void* const* d_in, const int* in_sizes, int n_in,
                              void* d_out, int out_size) {
    const float* f       = (const float*)d_in[0];   // (B,C,D)
    const float* p       = (const float*)d_in[1];   // (C,D)
    const int*   targets = (const int*)  d_in[2];   // (B,C)
    const float* rsc     = (const float*)d_in[3];   // (B,C)
    float* out = (float*)d_out;

    cudaFuncSetAttribute(k_gemm_mma, cudaFuncAttributeMaxDynamicSharedMemorySize, DYN_SMEM);

    k_prep<<<CC + BB, 256>>>(p, targets, rsc);
    k_norm_f<<<MAXP, 128>>>(f);
    k_gemm_mma<<<dim3(BB, CC / 128), 256, DYN_SMEM>>>();
    k_select<<<MAXP / 2, 256>>>(targets);
    k_final<<<1, 512>>>(out);
}

// round 17
// speedup vs baseline: 1.0780x; 1.0480x over previous
#include <cuda_runtime.h>
#include <cuda_bf16.h>
#include <math.h>
#include <stdint.h>

// Problem constants
#define BB 16
#define CC 1024
#define DD 768
#define TAU_INV 10.0f
#define KHARD 306
#define KRAND 717
#define SLOTS_PER_B 128
#define MAXP (BB * SLOTS_PER_B)   // 2048

// Split-bf16: rows stored as [hi|lo], K=1536 bf16 = 3072 B/row.
// GEMM: 12 physical k-chunks; each loads hiA/loA/hiB/loB tiles once and runs
// 3 MMA passes (hiA.hiB + hiA.loB + loA.hiB) from the same smem.
#define ROWB 3072
#define NPHYS 12
#define TB 16384                  // one 128x128B tile
#define STAGE_BYTES (4 * TB)      // 64 KB: hiA loA hiB loB
#define NSTAGE 3
#define DYN_SMEM (NSTAGE * STAGE_BYTES)   // 192 KB

// Static device scratch (zero-init at load; unused slot rows never written)
__device__ __align__(128) unsigned char g_Ab[(size_t)MAXP * ROWB];   // 6.3 MB
__device__ __align__(128) unsigned char g_Bb[(size_t)CC * ROWB];     // 3.1 MB
__device__ float g_S[(size_t)MAXP * CC];
__device__ int   g_posList[MAXP];
__device__ int   g_posCount[BB];
__device__ unsigned char g_randFlag[BB * CC];
__device__ float g_term[MAXP];

// ---------------------------------------------------------------------------
// helpers
// ---------------------------------------------------------------------------
__device__ __forceinline__ uint32_t smem_u32(const void* p) {
    uint32_t a;
    asm("{ .reg .u64 t; cvta.to.shared.u64 t, %1; cvt.u32.u64 %0, t; }" : "=r"(a) : "l"(p));
    return a;
}
__device__ __forceinline__ void cp16(uint32_t dst, const void* src) {
    asm volatile("cp.async.ca.shared.global [%0], [%1], 16;" :: "r"(dst), "l"(src) : "memory");
}
__device__ __forceinline__ void ldsm_x4(uint32_t& r0, uint32_t& r1, uint32_t& r2, uint32_t& r3,
                                        uint32_t a) {
    asm volatile("ldmatrix.sync.aligned.m8n8.x4.shared.b16 {%0,%1,%2,%3}, [%4];"
                 : "=r"(r0), "=r"(r1), "=r"(r2), "=r"(r3) : "r"(a));
}
__device__ __forceinline__ void ldsm_x2(uint32_t& r0, uint32_t& r1, uint32_t a) {
    asm volatile("ldmatrix.sync.aligned.m8n8.x2.shared.b16 {%0,%1}, [%2];"
                 : "=r"(r0), "=r"(r1) : "r"(a));
}
__device__ __forceinline__ void mma16816(float* c, const uint32_t* a, const uint32_t* b) {
    asm volatile("mma.sync.aligned.m16n8k16.row.col.f32.bf16.bf16.f32 "
                 "{%0,%1,%2,%3}, {%4,%5,%6,%7}, {%8,%9}, {%0,%1,%2,%3};"
                 : "+f"(c[0]), "+f"(c[1]), "+f"(c[2]), "+f"(c[3])
                 : "r"(a[0]), "r"(a[1]), "r"(a[2]), "r"(a[3]), "r"(b[0]), "r"(b[1]));
}
// order-preserving float<->uint key
__device__ __forceinline__ unsigned fkey(float f) {
    unsigned u = __float_as_uint(f);
    return (u & 0x80000000u) ? ~u : (u | 0x80000000u);
}
__device__ __forceinline__ float funkey(unsigned u) {
    return __uint_as_float((u & 0x80000000u) ? (u & 0x7fffffffu) : ~u);
}

union BF8 { __nv_bfloat16 h[8]; uint4 u; };

// ---------------------------------------------------------------------------
// Kernel 0 (fused): blocks [0,CC): normalize proto row, split bf16, write
// g_Bb row [hi|lo]. Blocks [CC,CC+BB): compaction + exact random top-KRAND
// via histogram descent run to step==1 (exact threshold key).
// ---------------------------------------------------------------------------
__global__ void k_prep(const float* __restrict__ p,
                       const int* __restrict__ targets,
                       const float* __restrict__ rsc) {
    int tid = threadIdx.x;
    if (blockIdx.x < CC) {
        int e = blockIdx.x;
        const float4* row = (const float4*)(p + (size_t)e * DD);
        float4 v0 = make_float4(0,0,0,0), v1 = make_float4(0,0,0,0);
        float ss = 0.f;
        if (tid < 96) {
            v0 = row[tid * 2]; v1 = row[tid * 2 + 1];
            ss = v0.x*v0.x + v0.y*v0.y + v0.z*v0.z + v0.w*v0.w
               + v1.x*v1.x + v1.y*v1.y + v1.z*v1.z + v1.w*v1.w;
        }
        for (int o = 16; o > 0; o >>= 1) ss += __shfl_xor_sync(0xffffffffu, ss, o);
        __shared__ float sW[8]; __shared__ float sInv;
        if ((tid & 31) == 0) sW[tid >> 5] = ss;
        __syncthreads();
        if (tid == 0) {
            float t = 0.f;
            for (int w = 0; w < 8; w++) t += sW[w];
            sInv = 1.0f / fmaxf(sqrtf(t), 1e-12f);
        }
        __syncthreads();
        if (tid < 96) {
            float inv = sInv;
            float v[8] = {v0.x*inv, v0.y*inv, v0.z*inv, v0.w*inv,
                          v1.x*inv, v1.y*inv, v1.z*inv, v1.w*inv};
            BF8 hi, lo;
#pragma unroll
            for (int j = 0; j < 8; j++) {
                hi.h[j] = __float2bfloat16(v[j]);
                lo.h[j] = __float2bfloat16(v[j] - __bfloat162float(hi.h[j]));
            }
            unsigned char* dst = g_Bb + (size_t)e * ROWB + tid * 16;
            *(uint4*)(dst)            = hi.u;   // hi segment
            *(uint4*)(dst + DD * 2)   = lo.u;   // lo segment
        }
        return;
    }

    // ---- per-batch compaction + exact random top-KRAND ----
    int b = blockIdx.x - CC;
    __shared__ unsigned int skey[CC];
    __shared__ unsigned char sfl[CC];
    __shared__ int hist[256];
    __shared__ int sW[8];
    __shared__ unsigned sWu[8];
    __shared__ int sQA[2];
    __shared__ int sOut;

    int lane = tid & 31, wid = tid >> 5;
    int e0 = tid * 4;
    unsigned int key[4]; int posf[4]; int cnt = 0;
#pragma unroll
    for (int j = 0; j < 4; j++) {
        int e = e0 + j;
        int isPos = (targets[b * CC + e] != 0);
        posf[j] = isPos; cnt += isPos;
        unsigned int k = isPos ? 0u : (__float_as_uint(rsc[b * CC + e]) + 1u);
        key[j] = k; skey[e] = k;
    }
    int inc = cnt;
    for (int o = 1; o < 32; o <<= 1) {
        int v = __shfl_up_sync(0xffffffffu, inc, o);
        if (lane >= o) inc += v;
    }
    if (lane == 31) sW[wid] = inc;
    __syncthreads();
    if (tid == 0) {
        int acc = 0;
        for (int w = 0; w < 8; w++) { int v = sW[w]; sW[w] = acc; acc += v; }
        g_posCount[b] = acc;
    }
    __syncthreads();
    int rank = sW[wid] + inc - cnt;
#pragma unroll
    for (int j = 0; j < 4; j++) {
        if (posf[j]) {
            if (rank < SLOTS_PER_B) g_posList[b * SLOTS_PER_B + rank] = e0 + j;
            rank++;
        }
    }

    // min (over negatives) / max of keys
    unsigned mk = max(max(key[0], key[1]), max(key[2], key[3]));
    unsigned nk0 = posf[0] ? 0xffffffffu : key[0];
    unsigned nk1 = posf[1] ? 0xffffffffu : key[1];
    unsigned nk2 = posf[2] ? 0xffffffffu : key[2];
    unsigned nk3 = posf[3] ? 0xffffffffu : key[3];
    unsigned nk = min(min(nk0, nk1), min(nk2, nk3));
    mk = __reduce_max_sync(0xffffffffu, mk);
    nk = __reduce_min_sync(0xffffffffu, nk);
    if (lane == 0) { sWu[wid] = mk; sW[wid] = (int)nk; }
    __syncthreads();
    unsigned mAll = sWu[0], nAll = (unsigned)sW[0];
#pragma unroll
    for (int w = 1; w < 8; w++) {
        mAll = max(mAll, sWu[w]);
        nAll = min(nAll, (unsigned)sW[w]);
    }

    // histogram descent to exact threshold (cell width 1); no trailing barrier
    unsigned lo = nAll;
    unsigned range = mAll - nAll + 1u;
    int above = 0;
    while (range > 1u) {
        unsigned step = range / 256u + 1u;
        hist[tid] = 0;
        __syncthreads();
#pragma unroll
        for (int j = 0; j < 4; j++) {
            unsigned d = key[j] - lo;            // wraps huge if key < lo
            if (d < range) atomicAdd(&hist[d / step], 1);
        }
        __syncthreads();
        if (wid == 0) {
            int h[8]; int ssum = 0;
            int base = lane * 8;
#pragma unroll
            for (int q = 0; q < 8; q++) { h[q] = hist[base + q]; ssum += h[q]; }
            int suf = ssum;
            for (int o = 1; o < 32; o <<= 1) {
                int v = __shfl_down_sync(0xffffffffu, suf, o);
                if (lane + o < 32) suf += v;
            }
            int hiAbove = above + suf - ssum;
            if (above + suf >= KRAND && hiAbove < KRAND) {   // exactly one lane
                int acc = hiAbove;
                int q = 7;
                for (; q > 0; q--) {
                    if (acc + h[q] >= KRAND) break;
                    acc += h[q];
                }
                sQA[0] = base + q;
                sQA[1] = acc;
            }
        }
        __syncthreads();
        lo = lo + (unsigned)sQA[0] * step;
        above = sQA[1];
        range = step;
    }
    unsigned V = lo;                              // exact KRAND-th largest key
    int n_gt = above;                             // exact count(key > V)
    int rrem = KRAND - n_gt;                      // ties needed at V (>=1)

    int ec = (key[0] == V) + (key[1] == V) + (key[2] == V) + (key[3] == V);
    ec = __reduce_add_sync(0xffffffffu, ec);
    if (lane == 0) sW[wid] = ec;
    __syncthreads();
    if (tid == 0) { int t = 0; for (int w = 0; w < 8; w++) t += sW[w]; sOut = t; }
    __syncthreads();
    int n_eq = sOut;

    if (n_eq == rrem) {
#pragma unroll
        for (int j = 0; j < 4; j++) sfl[e0 + j] = (key[j] >= V) ? 1 : 0;
        __syncthreads();
    } else {
#pragma unroll
        for (int j = 0; j < 4; j++) sfl[e0 + j] = (key[j] > V) ? 1 : 0;
        __syncthreads();
        if (tid == 0) {
            int rem = rrem;
            for (int e = 0; e < CC && rem > 0; e++)
                if (skey[e] == V) { sfl[e] = 1; rem--; }
        }
        __syncthreads();
    }
#pragma unroll
    for (int j = 0; j < 4; j++) g_randFlag[b * CC + e0 + j] = sfl[e0 + j];
}

// ---------------------------------------------------------------------------
// Kernel 1: gather + normalize positive anchor rows, split bf16, write
// g_Ab row [hi|lo].
// ---------------------------------------------------------------------------
__global__ void k_norm_f(const float* __restrict__ f) {
    int i = blockIdx.x;
    int b = i >> 7, r = i & 127;
    int cnt = g_posCount[b]; if (cnt > SLOTS_PER_B) cnt = SLOTS_PER_B;
    if (r >= cnt) return;
    int c = g_posList[i];
    int tid = threadIdx.x;

    const float4* src = (const float4*)(f + (size_t)(b * CC + c) * DD);
    float4 v0 = make_float4(0,0,0,0), v1 = make_float4(0,0,0,0);
    float ss = 0.f;
    if (tid < 96) {
        v0 = src[tid * 2]; v1 = src[tid * 2 + 1];
        ss = v0.x*v0.x + v0.y*v0.y + v0.z*v0.z + v0.w*v0.w
           + v1.x*v1.x + v1.y*v1.y + v1.z*v1.z + v1.w*v1.w;
    }
    for (int o = 16; o > 0; o >>= 1) ss += __shfl_xor_sync(0xffffffffu, ss, o);
    __shared__ float sW[4]; __shared__ float sInv;
    if ((tid & 31) == 0) sW[tid >> 5] = ss;
    __syncthreads();
    if (tid == 0) sInv = 1.0f / fmaxf(sqrtf(sW[0]+sW[1]+sW[2]+sW[3]), 1e-12f);
    __syncthreads();
    if (tid >= 96) return;
    float inv = sInv;
    float v[8] = {v0.x*inv, v0.y*inv, v0.z*inv, v0.w*inv,
                  v1.x*inv, v1.y*inv, v1.z*inv, v1.w*inv};
    BF8 hi, lo;
#pragma unroll
    for (int j = 0; j < 8; j++) {
        hi.h[j] = __float2bfloat16(v[j]);
        lo.h[j] = __float2bfloat16(v[j] - __bfloat162float(hi.h[j]));
    }
    unsigned char* dst = g_Ab + (size_t)i * ROWB + tid * 16;
    *(uint4*)(dst)            = hi.u;   // hi segment
    *(uint4*)(dst + DD * 2)   = lo.u;   // lo segment
}

// ---------------------------------------------------------------------------
// Kernel 2: bf16 tensor-core GEMM via mma.sync m16n8k16.
// 12 physical chunks; each loads 4 tiles (hiA,loA,hiB,loB) ONCE and runs
// 3 accumulate passes -> 98 MB L2 traffic. Grid (16, 8), 256 thr,
// 3-stage cp.async pipeline, 1 barrier/chunk.
// ---------------------------------------------------------------------------
__global__ void __launch_bounds__(256, 1) k_gemm_mma() {
    extern __shared__ __align__(16) unsigned char dynsm[];
    int m = blockIdx.x;
    int cnt = g_posCount[m]; if (cnt <= 0) return;
    if (cnt > SLOTS_PER_B) cnt = SLOTS_PER_B;
    int eBase = blockIdx.y * 128;

    int tid = threadIdx.x, lane = tid & 31, wid = tid >> 5;
    int wm = (wid & 1) * 64, wn = (wid >> 1) * 32;

    uint32_t sbase = smem_u32(dynsm);
    const unsigned char* gA = g_Ab + (size_t)m * 128 * ROWB;
    const unsigned char* gB = g_Bb + (size_t)eBase * ROWB;

    float acc[4][4][4];
#pragma unroll
    for (int i = 0; i < 4; i++)
#pragma unroll
        for (int j = 0; j < 4; j++)
#pragma unroll
            for (int q = 0; q < 4; q++) acc[i][j][q] = 0.f;

    auto copy_chunk = [&](int c, int st) {
        uint32_t sb = sbase + st * STAGE_BYTES;
        int hiOff = c * 128, loOff = (NPHYS + c) * 128;
#pragma unroll
        for (int i = 0; i < 4; i++) {
            int idx = tid + i * 256;
            int row = idx >> 3, seg = idx & 7;
            uint32_t so = (uint32_t)((row << 3) + (seg ^ (row & 7))) * 16;
            size_t rbA = (size_t)row * ROWB + seg * 16;
            cp16(sb + so,          gA + rbA + hiOff);   // hiA
            cp16(sb + TB + so,     gA + rbA + loOff);   // loA
            cp16(sb + 2*TB + so,   gB + rbA + hiOff);   // hiB
            cp16(sb + 3*TB + so,   gB + rbA + loOff);   // loB
        }
        asm volatile("cp.async.commit_group;" ::: "memory");
    };

    copy_chunk(0, 0);
    copy_chunk(1, 1);

    for (int c = 0; c < NPHYS; c++) {
        if (c + 1 < NPHYS)
            asm volatile("cp.async.wait_group 1;" ::: "memory");
        else
            asm volatile("cp.async.wait_group 0;" ::: "memory");
        __syncthreads();
        if (c + 2 < NPHYS) copy_chunk(c + 2, (c + 2) % 3);

        uint32_t sb = sbase + (c % 3) * STAGE_BYTES;
        uint32_t sHiA = sb, sLoA = sb + TB, sHiB = sb + 2*TB, sLoB = sb + 3*TB;
#pragma unroll
        for (int ks = 0; ks < 4; ks++) {
            uint32_t aH[4][4], aL[4][4], bH[4][2], bL[4][2];
#pragma unroll
            for (int mi = 0; mi < 4; mi++) {
                int row = wm + mi * 16 + (lane & 15);
                int kseg = 2 * ks + (lane >> 4);
                uint32_t off = (uint32_t)((row << 3) + (kseg ^ (row & 7))) * 16;
                ldsm_x4(aH[mi][0], aH[mi][1], aH[mi][2], aH[mi][3], sHiA + off);
                ldsm_x4(aL[mi][0], aL[mi][1], aL[mi][2], aL[mi][3], sLoA + off);
            }
#pragma unroll
            for (int ni = 0; ni < 4; ni++) {
                int rn = wn + ni * 8 + (lane & 7);
                int kseg = 2 * ks + ((lane >> 3) & 1);
                uint32_t off = (uint32_t)((rn << 3) + (kseg ^ (rn & 7))) * 16;
                ldsm_x2(bH[ni][0], bH[ni][1], sHiB + off);
                ldsm_x2(bL[ni][0], bL[ni][1], sLoB + off);
            }
#pragma unroll
            for (int mi = 0; mi < 4; mi++)
#pragma unroll
                for (int ni = 0; ni < 4; ni++) {
                    mma16816(acc[mi][ni], aH[mi], bH[ni]);   // hi.hi
                    mma16816(acc[mi][ni], aH[mi], bL[ni]);   // hi.lo
                    mma16816(acc[mi][ni], aL[mi], bH[ni]);   // lo.hi
                }
        }
    }

    int qr = lane >> 2, qc = (lane & 3) * 2;
#pragma unroll
    for (int mi = 0; mi < 4; mi++) {
#pragma unroll
        for (int ni = 0; ni < 4; ni++) {
            int r0 = wm + mi * 16 + qr;
            int col = eBase + wn + ni * 8 + qc;
            if (r0 < cnt)
                *(float2*)(g_S + (size_t)(m * 128 + r0) * CC + col)
                    = make_float2(acc[mi][ni][0], acc[mi][ni][1]);
            if (r0 + 8 < cnt)
                *(float2*)(g_S + (size_t)(m * 128 + r0 + 8) * CC + col)
                    = make_float2(acc[mi][ni][2], acc[mi][ni][3]);
        }
    }
}

// ---------------------------------------------------------------------------
// Kernel 3: per positive anchor: top-KHARD exp-sum via 3-pass 256-bin
// histogram descent + random-set exp sum -> loss term.
// ---------------------------------------------------------------------------
__global__ void k_select(const int* __restrict__ targets) {
    int i = blockIdx.x;
    int b = i >> 7, r = i & 127;
    int cnt = g_posCount[b]; if (cnt > SLOTS_PER_B) cnt = SLOTS_PER_B;
    int tid = threadIdx.x;
    if (r >= cnt) { if (tid == 0) g_term[i] = 0.f; return; }
    int c = g_posList[i];

    __shared__ int hist[256];
    __shared__ unsigned sWmax[8];
    __shared__ unsigned sWmin[8];
    __shared__ int sQA[2];
    __shared__ float sWf[8];

    int lane = tid & 31, wid = tid >> 5;

    float4 sa = *((const float4*)(g_S + (size_t)i * CC) + tid);
    int4   t4 = *((const int4*)(targets + b * CC) + tid);
    uchar4 r4 = *((const uchar4*)(g_randFlag + b * CC) + tid);
    float s[4] = {sa.x, sa.y, sa.z, sa.w};
    int neg[4] = {t4.x == 0, t4.y == 0, t4.z == 0, t4.w == 0};
    int fl[4]  = {r4.x, r4.y, r4.z, r4.w};
    unsigned key[4];
#pragma unroll
    for (int j = 0; j < 4; j++) key[j] = neg[j] ? fkey(s[j]) : 0u;

    unsigned mk = max(max(key[0], key[1]), max(key[2], key[3]));
    unsigned nk0 = neg[0] ? key[0] : 0xffffffffu;
    unsigned nk1 = neg[1] ? key[1] : 0xffffffffu;
    unsigned nk2 = neg[2] ? key[2] : 0xffffffffu;
    unsigned nk3 = neg[3] ? key[3] : 0xffffffffu;
    unsigned nk = min(min(nk0, nk1), min(nk2, nk3));
    mk = __reduce_max_sync(0xffffffffu, mk);
    nk = __reduce_min_sync(0xffffffffu, nk);
    if (lane == 0) { sWmax[wid] = mk; sWmin[wid] = nk; }
    __syncthreads();
    unsigned mAll = sWmax[0], nAll = sWmin[0];
#pragma unroll
    for (int w = 1; w < 8; w++) { mAll = max(mAll, sWmax[w]); nAll = min(nAll, sWmin[w]); }
    float M = funkey(mAll);

    // 3-pass histogram descent; no trailing barrier
    unsigned lo = nAll;
    unsigned range = mAll - nAll + 1u;
    unsigned step = 1u;
    int above = 0;
#pragma unroll
    for (int pass = 0; pass < 3; pass++) {
        step = range / 256u + 1u;
        hist[tid] = 0;
        __syncthreads();
#pragma unroll
        for (int j = 0; j < 4; j++) {
            unsigned d = key[j] - lo;            // wraps huge if key < lo
            if (d < range) atomicAdd(&hist[d / step], 1);
        }
        __syncthreads();
        if (wid == 0) {
            int h[8]; int ssum = 0;
            int base = lane * 8;
#pragma unroll
            for (int q = 0; q < 8; q++) { h[q] = hist[base + q]; ssum += h[q]; }
            int suf = ssum;
            for (int o = 1; o < 32; o <<= 1) {
                int v = __shfl_down_sync(0xffffffffu, suf, o);
                if (lane + o < 32) suf += v;
            }
            int hiAbove = above + suf - ssum;
            if (above + suf >= KHARD && hiAbove < KHARD) {   // exactly one lane
                int acc = hiAbove;
                int q = 7;
                for (; q > 0; q--) {
                    if (acc + h[q] >= KHARD) break;
                    acc += h[q];
                }
                sQA[0] = base + q;
                sQA[1] = acc;
            }
        }
        __syncthreads();
        int Q = sQA[0]; above = sQA[1];
        lo = lo + (unsigned)Q * step;
        range = step;
    }
    unsigned Hi = lo + step;
    int rem = KHARD - above;                     // >= 1 ties in [lo, Hi)

    float es = 0.f;
#pragma unroll
    for (int j = 0; j < 4; j++) {
        float e = __expf((s[j] - M) * TAU_INV);
        if (key[j] >= Hi) es += e;
        if (fl[j])        es += e;
    }
    for (int o = 16; o > 0; o >>= 1) es += __shfl_xor_sync(0xffffffffu, es, o);
    if (lane == 0) sWf[wid] = es;
    __syncthreads();

    if (tid == 0) {
        float su = sWf[0]+sWf[1]+sWf[2]+sWf[3]+sWf[4]+sWf[5]+sWf[6]+sWf[7];
        su += (float)rem * __expf((funkey(lo) - M) * TAU_INV);
        float pos = g_S[(size_t)i * CC + c] * TAU_INV;
        float lse = M * TAU_INV + __logf(su);
        float d = lse - pos;
        float term = (d > 0.f) ? d + log1pf(__expf(-d)) : log1pf(__expf(d));
        g_term[i] = term;
    }
}

// ---------------------------------------------------------------------------
// Kernel 4: deterministic final reduction -> scalar loss
// ---------------------------------------------------------------------------
__global__ void k_final(float* __restrict__ out) {
    __shared__ float sbs[BB];
    int wid = threadIdx.x >> 5, lane = threadIdx.x & 31;
    float s = 0.f;
    for (int r = lane; r < SLOTS_PER_B; r += 32) s += g_term[wid * SLOTS_PER_B + r];
    for (int o = 16; o > 0; o >>= 1) s += __shfl_xor_sync(0xffffffffu, s, o);
    if (lane == 0) sbs[wid] = s;
    __syncthreads();
    if (threadIdx.x == 0) {
        float tot = 0.f;
        for (int b = 0; b < BB; b++) {
            int pc = g_posCount[b]; if (pc < 1) pc = 1;
            tot += sbs[b] / (float)pc;
        }
        out[0] = tot / (float)BB;
    }
}

extern "C" void kernel_launch(void* const* d_in, const int* in_sizes, int n_in,
                              void* d_out, int out_size) {
    const float* f       = (const float*)d_in[0];   // (B,C,D)
    const float* p       = (const float*)d_in[1];   // (C,D)
    const int*   targets = (const int*)  d_in[2];   // (B,C)
    const float* rsc     = (const float*)d_in[3];   // (B,C)
    float* out = (float*)d_out;

    cudaFuncSetAttribute(k_gemm_mma, cudaFuncAttributeMaxDynamicSharedMemorySize, DYN_SMEM);

    k_prep<<<CC + BB, 256>>>(p, targets, rsc);
    k_norm_f<<<MAXP, 128>>>(f);
    k_gemm_mma<<<dim3(BB, CC / 128), 256, DYN_SMEM>>>();
    k_select<<<MAXP, 256>>>(targets);
    k_final<<<1, 512>>>(out);
}